// round 4
// baseline (speedup 1.0000x reference)
#include <cuda_runtime.h>
#include <cstdint>

typedef unsigned long long u64;

#define HW 65536           // 256*256
#define NB 8
#define NC 32
#define NBC 256

__device__ __align__(16) float g_feat[NB * NC * HW];
__device__ float g_pp[NBC * 4 * 25];
__device__ float g_filt[NBC * 25];

__device__ __forceinline__ u64 fma2(u64 a, u64 b, u64 c) {
    u64 d;
    asm("fma.rn.f32x2 %0, %1, %2, %3;" : "=l"(d) : "l"(a), "l"(b), "l"(c));
    return d;
}
__device__ __forceinline__ u64 dup(float f) {
    unsigned u = __float_as_uint(f);
    return ((u64)u << 32) | (u64)u;
}

// ---------------------------------------------------------------------------
// Kernel 1: channel mix (1x1 conv), register-blocked 4 pixel-pairs x 8 och
// per thread. Weights stored i-major (transposed) + duplicated in SMEM so
// per-i loads are 4 LDS.128 on distinct banks; x pairs are 2 LDS.128.
// Per i-step: 6 LSU ops + 32 fma2  -> fma2-bound.
// grid = (128, 8), block = 256, dyn smem = 73984 B -> 2 blocks/SM
// ---------------------------------------------------------------------------
__global__ __launch_bounds__(256, 2) void mix_kernel(
    const float* __restrict__ x,
    const float* __restrict__ w,
    const float* __restrict__ bias)
{
    extern __shared__ ulonglong2 smq[];
    ulonglong2* xsq = smq;                 // [32][128] pixel pairs (2 per elem)
    ulonglong2* wq  = smq + 32 * 128;      // [32 i][16] = w2t[i][o] pairs
    u64*        b2  = (u64*)(wq + 32 * 16);// [32]

    int tid = threadIdx.x;
    for (int idx = tid; idx < 1024; idx += 256) {
        int i = idx >> 5, o = idx & 31;
        ((u64*)wq)[i * 32 + o] = dup(w[o * 32 + i]);   // transpose
    }
    if (tid < 32)
        b2[tid] = dup(bias[tid]);

    int b = blockIdx.y;
    const ulonglong2* xb =
        (const ulonglong2*)(x + (size_t)b * (NC * HW) + blockIdx.x * 512);
#pragma unroll
    for (int k = 0; k < 16; k++) {
        int e = tid + k * 256;
        int i = e >> 7;
        int c = e & 127;
        xsq[i * 128 + c] = xb[(size_t)i * (HW / 4) + c];
    }
    __syncthreads();

    int og = tid & 3;          // 8 output channels starting og*8
    int pg = tid >> 2;         // 4 pixel pairs starting pg*4

    u64 acc[32];               // acc[p*8+k]
#pragma unroll
    for (int k = 0; k < 8; k++) {
        u64 bv = b2[og * 8 + k];
#pragma unroll
        for (int p = 0; p < 4; p++) acc[p * 8 + k] = bv;
    }

#pragma unroll 8
    for (int i = 0; i < 32; i++) {
        ulonglong2 xa = xsq[i * 128 + pg * 2];
        ulonglong2 xc = xsq[i * 128 + pg * 2 + 1];
        u64 xv[4] = {xa.x, xa.y, xc.x, xc.y};
        ulonglong2 w0 = wq[i * 16 + og * 4 + 0];
        ulonglong2 w1 = wq[i * 16 + og * 4 + 1];
        ulonglong2 w2 = wq[i * 16 + og * 4 + 2];
        ulonglong2 w3 = wq[i * 16 + og * 4 + 3];
        u64 wv[8] = {w0.x, w0.y, w1.x, w1.y, w2.x, w2.y, w3.x, w3.y};
#pragma unroll
        for (int p = 0; p < 4; p++)
#pragma unroll
            for (int k = 0; k < 8; k++)
                acc[p * 8 + k] = fma2(wv[k], xv[p], acc[p * 8 + k]);
    }

    u64* fb = (u64*)g_feat + (size_t)b * (NC * (HW / 2))
            + blockIdx.x * 256 + pg * 4;
#pragma unroll
    for (int k = 0; k < 8; k++) {
        u64* cp = fb + (size_t)(og * 8 + k) * (HW / 2);
        *(ulonglong2*)cp       = make_ulonglong2(acc[0 * 8 + k], acc[1 * 8 + k]);
        *((ulonglong2*)cp + 1) = make_ulonglong2(acc[2 * 8 + k], acc[3 * 8 + k]);
    }
}

// ---------------------------------------------------------------------------
// Kernel 2: adaptive pool partials on x (pooling commutes with the 1x1 conv).
// Row bins [0,52)[51,103)[102,154)[153,205)[204,256) (overlapping).
// grid = (256, 4 row-chunks), block = 256 (thread = column)
// ---------------------------------------------------------------------------
__global__ __launch_bounds__(256) void pool_kernel(const float* __restrict__ x)
{
    __shared__ float pool[25];
    int bc = blockIdx.x;
    int q  = blockIdx.y;
    int w  = threadIdx.x;
    if (w < 25) pool[w] = 0.0f;
    __syncthreads();

    const float* img = x + (size_t)bc * HW + (size_t)q * 64 * 256;

    float cs[5] = {0.f, 0.f, 0.f, 0.f, 0.f};
#pragma unroll
    for (int r = 0; r < 64; r++) {
        int h = q * 64 + r;
        float v = img[r * 256 + w];
        if (h < 52)              cs[0] += v;
        if (h >= 51 && h < 103)  cs[1] += v;
        if (h >= 102 && h < 154) cs[2] += v;
        if (h >= 153 && h < 205) cs[3] += v;
        if (h >= 204)            cs[4] += v;
    }

#pragma unroll
    for (int l = 0; l < 5; l++) {
        int s = (l * 256) / 5;
        int e = ((l + 1) * 256 + 4) / 5;
        if (w >= s && w < e) {
#pragma unroll
            for (int k = 0; k < 5; k++)
                if (cs[k] != 0.0f)
                    atomicAdd(&pool[k * 5 + l], cs[k]);
        }
    }
    __syncthreads();
    if (w < 25)
        g_pp[(bc * 4 + q) * 25 + w] = pool[w];
}

// ---------------------------------------------------------------------------
// Kernel 3: filt[b,o,kl] = bias[o] + sum_i w[o,i] * px[b,i,kl]
// grid = 8, block = 800
// ---------------------------------------------------------------------------
__global__ void filt_kernel(const float* __restrict__ w,
                            const float* __restrict__ bias)
{
    __shared__ float spx[800];
    int b = blockIdx.x;
    int t = threadIdx.x;
    int i  = t / 25;
    int kl = t - i * 25;

    float s = 0.0f;
#pragma unroll
    for (int q = 0; q < 4; q++)
        s += g_pp[((b * 32 + i) * 4 + q) * 25 + kl];
    spx[t] = s * (1.0f / 2704.0f);
    __syncthreads();

    float acc = bias[i];
#pragma unroll
    for (int ic = 0; ic < 32; ic++)
        acc += w[i * 32 + ic] * spx[ic * 25 + kl];
    g_filt[b * 800 + t] = acc;
}

// ---------------------------------------------------------------------------
// Kernel 4: depthwise 5x5 'same' conv, packed f32x2, spill-free.
// ky-outer loop: only one duplicated filter row (10 regs) live at a time.
// Two SMEM copies of the tile (second shifted by one column) make ALL 5
// kx taps aligned LDS.64 -> zero pack MOVs. 64x64 tile, 2x8 patch/thread.
// grid = (16, 256), block = 256, smem = 37.2 KB
// ---------------------------------------------------------------------------
__global__ __launch_bounds__(256, 4) void conv_kernel(float* __restrict__ out)
{
    __shared__ float sh [68 * 68];
    __shared__ float sh2[68 * 68];      // sh2[r][c] = sh[r][c+1]
    __shared__ u64   sf2[25];

    int bc  = blockIdx.y;
    int tx0 = (blockIdx.x & 3) * 64;
    int ty0 = (blockIdx.x >> 2) * 64;

    if (threadIdx.x < 25)
        sf2[threadIdx.x] = dup(g_filt[bc * 25 + threadIdx.x]);

    const float* img = g_feat + (size_t)bc * HW;
    for (int idx = threadIdx.x; idx < 68 * 68; idx += 256) {
        int r = idx / 68;
        int c = idx - r * 68;
        int gy = ty0 + r - 2;
        int gx = tx0 + c - 2;
        float v = 0.0f;
        if ((unsigned)gy < 256u && (unsigned)gx < 256u)
            v = img[gy * 256 + gx];
        sh[idx] = v;
        if (c >= 1) sh2[idx - 1] = v;
    }
    __syncthreads();

    int x  = (threadIdx.x & 31) * 2;    // output col pair (even)
    int oy = (threadIdx.x >> 5) * 8;    // first output row

    u64 acc[8];
#pragma unroll
    for (int j = 0; j < 8; j++) acc[j] = 0ull;

#pragma unroll
    for (int ky = 0; ky < 5; ky++) {
        u64 f0 = sf2[ky * 5 + 0];
        u64 f1 = sf2[ky * 5 + 1];
        u64 f2 = sf2[ky * 5 + 2];
        u64 f3 = sf2[ky * 5 + 3];
        u64 f4 = sf2[ky * 5 + 4];
#pragma unroll
        for (int j = 0; j < 8; j++) {
            int off = (oy + j + ky) * 68 + x;
            acc[j] = fma2(f0, *(const u64*)(sh  + off),     acc[j]);
            acc[j] = fma2(f1, *(const u64*)(sh2 + off),     acc[j]);
            acc[j] = fma2(f2, *(const u64*)(sh  + off + 2), acc[j]);
            acc[j] = fma2(f3, *(const u64*)(sh2 + off + 2), acc[j]);
            acc[j] = fma2(f4, *(const u64*)(sh  + off + 4), acc[j]);
        }
    }

    float* op = out + (size_t)bc * HW + (size_t)(ty0 + oy) * 256 + tx0 + x;
#pragma unroll
    for (int j = 0; j < 8; j++)
        *(u64*)(op + (size_t)j * 256) = acc[j];
}

// ---------------------------------------------------------------------------
extern "C" void kernel_launch(void* const* d_in, const int* in_sizes, int n_in,
                              void* d_out, int out_size)
{
    const float* x    = (const float*)d_in[0];   // [8, 32, 256, 256]
    const float* w    = (const float*)d_in[1];   // [32, 32]
    const float* bias = (const float*)d_in[2];   // [32]
    float* out = (float*)d_out;                  // [8, 32, 256, 256]

    const int mix_smem = 32 * 128 * 16 + 32 * 16 * 16 + 32 * 8;   // 73984 B
    cudaFuncSetAttribute(mix_kernel,
                         cudaFuncAttributeMaxDynamicSharedMemorySize, mix_smem);

    pool_kernel<<<dim3(NBC, 4), 256>>>(x);
    mix_kernel<<<dim3(128, NB), 256, mix_smem>>>(x, w, bias);
    filt_kernel<<<NB, 800>>>(w, bias);
    conv_kernel<<<dim3(16, NBC), 256>>>(out);
}